// round 2
// baseline (speedup 1.0000x reference)
#include <cuda_runtime.h>
#include <cuda_bf16.h>
#include <math.h>

// Problem constants
#define BB   16
#define SS   1024
#define EE   256
#define HH   256
#define G4H  1024
#define WT   256
#define MM   (BB * SS)   // 16384 rows for all big GEMMs

// ---------------------------------------------------------------------------
// Scratch (device globals; allocation-free per harness rules)
// ---------------------------------------------------------------------------
__device__ float g_pre_f[MM * G4H];   // x@Wih_f + b_f
__device__ float g_pre_b[MM * G4H];   // x@Wih_b + b_b
__device__ float g_pre_d[MM * G4H];   // shifted [x,hn]@dec_Wih + dec_b
__device__ float g_hn[MM * HH];       // fwd encoder hiddens
__device__ float g_hb[MM * HH];       // bwd encoder hiddens
__device__ float g_dh[MM * HH];       // decoder hiddens
__device__ float g_q [MM * WT];       // hn@W1a + hb@W1b + x@W2   (per-position j)
__device__ float g_p [MM * WT];       // x@W3 + dh@W4             (per-step t)
__device__ float g_hcur[2 * BB * HH]; // double-buffered current h
__device__ unsigned g_bar_cnt;        // monotonic grid-barrier counter

// ---------------------------------------------------------------------------
// Monotonic grid barrier (all blocks co-resident; no reset needed)
// ---------------------------------------------------------------------------
__device__ __forceinline__ void grid_barrier(unsigned nb) {
    __syncthreads();
    if (threadIdx.x == 0) {
        __threadfence();
        unsigned a = atomicAdd(&g_bar_cnt, 1u);
        unsigned target = a - (a % nb) + nb;
        while (*(volatile unsigned*)&g_bar_cnt < target) __nanosleep(64);
    }
    __syncthreads();
}

// ---------------------------------------------------------------------------
// Tiled fp32 GEMM: C[M,N] (= or +=) A[M,K] @ Bw[K,N] (+ bias on first pass)
// shiftA: logical row m reads A[m-1]; rows with (m % SS)==0 read zeros.
// ---------------------------------------------------------------------------
#define GBM 128
#define GBN 64
#define GBK 16

__global__ __launch_bounds__(256) void gemm_kernel(
    const float* __restrict__ A, const float* __restrict__ Bw,
    const float* __restrict__ bias, float* __restrict__ C,
    int N, int K, int shiftA, int accFlag)
{
    __shared__ __align__(16) float As[GBK][GBM + 4];
    __shared__ __align__(16) float Bs[GBK][GBN];
    const int bm  = blockIdx.y * GBM;
    const int bn  = blockIdx.x * GBN;
    const int tid = threadIdx.x;
    const int tx  = tid & 15;   // n-subtile (4 cols)
    const int ty  = tid >> 4;   // m-subtile (8 rows)

    float acc[8][4];
#pragma unroll
    for (int i = 0; i < 8; i++)
#pragma unroll
        for (int j = 0; j < 4; j++) acc[i][j] = 0.f;

    for (int k0 = 0; k0 < K; k0 += GBK) {
        // load B tile [16 x 64]
        {
            int kr = tid >> 4;
            int cq = tid & 15;
            float4 v = *(const float4*)(Bw + (size_t)(k0 + kr) * N + bn + cq * 4);
            *(float4*)(&Bs[kr][cq * 4]) = v;
        }
        // load A tile [128 rows x 16 k] transposed into As[k][m]
#pragma unroll
        for (int l = 0; l < 2; l++) {
            int f4 = tid + l * 256;
            int r  = f4 >> 2;        // 0..127
            int kq = f4 & 3;         // which float4 in k
            int gm = bm + r;
            float4 v;
            if (shiftA && ((gm & (SS - 1)) == 0)) {
                v = make_float4(0.f, 0.f, 0.f, 0.f);
            } else {
                v = *(const float4*)(A + (size_t)(gm - shiftA) * K + k0 + kq * 4);
            }
            As[kq * 4 + 0][r] = v.x;
            As[kq * 4 + 1][r] = v.y;
            As[kq * 4 + 2][r] = v.z;
            As[kq * 4 + 3][r] = v.w;
        }
        __syncthreads();
#pragma unroll
        for (int kk = 0; kk < GBK; kk++) {
            float4 a0 = *(const float4*)(&As[kk][ty * 8]);
            float4 a1 = *(const float4*)(&As[kk][ty * 8 + 4]);
            float4 bv = *(const float4*)(&Bs[kk][tx * 4]);
            float am[8] = {a0.x, a0.y, a0.z, a0.w, a1.x, a1.y, a1.z, a1.w};
            float bmv[4] = {bv.x, bv.y, bv.z, bv.w};
#pragma unroll
            for (int i = 0; i < 8; i++)
#pragma unroll
                for (int j = 0; j < 4; j++) acc[i][j] += am[i] * bmv[j];
        }
        __syncthreads();
    }

    float4 bias4 = make_float4(0.f, 0.f, 0.f, 0.f);
    if (!accFlag && bias) bias4 = *(const float4*)(bias + bn + tx * 4);
#pragma unroll
    for (int i = 0; i < 8; i++) {
        int gm = bm + ty * 8 + i;
        float* crow = C + (size_t)gm * N + bn + tx * 4;
        float4 v = make_float4(acc[i][0], acc[i][1], acc[i][2], acc[i][3]);
        if (accFlag) {
            float4 old = *(const float4*)crow;
            v.x += old.x; v.y += old.y; v.z += old.z; v.w += old.w;
        } else {
            v.x += bias4.x; v.y += bias4.y; v.z += bias4.z; v.w += bias4.w;
        }
        *(float4*)crow = v;
    }
}

// ---------------------------------------------------------------------------
// Persistent LSTM recurrence.
// 128 blocks = 16 batches x 8 unit-slices (32 units each -> 128 z-columns:
// [i(32) f(32) g(32) o(32)]). 512 threads: c = tid&127 (column),
// kh = tid>>7 (k-split of 4 x 64). Whh slice register-resident (64 f/thread).
// h exchanged via double-buffered global (L2), monotonic grid barrier.
// ---------------------------------------------------------------------------
__device__ __forceinline__ float sigm(float x) {
    return 1.0f / (1.0f + expf(-x));
}

__global__ __launch_bounds__(512, 1) void lstm_kernel(
    const float* __restrict__ pre,    // [B,S,4H]
    const float* __restrict__ Whh,    // [H,4H]
    float* __restrict__ hout,         // [B,S,H]
    const float* __restrict__ cinit,  // null, or [B,S,H]: c0 = cinit[b,S-1,:]
    int backward)
{
    const int blk   = blockIdx.x;      // 0..127
    const int batch = blk >> 3;
    const int slice = blk & 7;
    const int tid   = threadIdx.x;
    const int c     = tid & 127;
    const int kh    = tid >> 7;
    const int gcol  = ((c >> 5) << 8) + (slice << 5) + (c & 31); // gate*256 + unit

    __shared__ float hs[HH];
    __shared__ float part[512];
    __shared__ float zs[128];

    // register-resident Whh slice
    float w[64];
#pragma unroll
    for (int j = 0; j < 64; j++)
        w[j] = Whh[(size_t)(kh * 64 + j) * G4H + gcol];

    // cell state (threads 0..31 own one unit each)
    float cst = 0.f;
    if (tid < 32 && cinit)
        cst = cinit[((size_t)batch * SS + (SS - 1)) * HH + (slice << 5) + tid];

    // zero h buffer 0 for this batch
    if (tid < HH) g_hcur[batch * HH + tid] = 0.f;
    __threadfence();
    grid_barrier(gridDim.x);

    for (int s = 0; s < SS; s++) {
        const int t = backward ? (SS - 1 - s) : s;

        // prefetch pre-activation (DRAM) — consumed after the matvec
        float preval = 0.f;
        if (tid < 128)
            preval = pre[((size_t)batch * SS + t) * G4H + gcol];

        // load h (L2, bypass L1) into smem
        const float4* hrd = (const float4*)(g_hcur + (s & 1) * (BB * HH) + batch * HH);
        if (tid < HH / 4)
            *(float4*)(&hs[tid * 4]) = __ldcg(hrd + tid);
        __syncthreads();

        // matvec partial: 64 k per thread
        float acc = 0.f;
        const float* hp = hs + kh * 64;
#pragma unroll
        for (int j4 = 0; j4 < 16; j4++) {
            float4 hv = *(const float4*)(hp + j4 * 4);
            acc += hv.x * w[j4 * 4 + 0];
            acc += hv.y * w[j4 * 4 + 1];
            acc += hv.z * w[j4 * 4 + 2];
            acc += hv.w * w[j4 * 4 + 3];
        }
        part[(kh << 7) + c] = acc;
        __syncthreads();

        if (tid < 128)
            zs[tid] = part[tid] + part[128 + tid] + part[256 + tid] + part[384 + tid] + preval;
        __syncthreads();

        if (tid < 32) {
            float zi = zs[tid], zf = zs[32 + tid], zg = zs[64 + tid], zo = zs[96 + tid];
            float c2 = sigm(zf) * cst + sigm(zi) * tanhf(zg);
            cst = c2;
            float h2 = sigm(zo) * tanhf(c2);
            int ucol = (slice << 5) + tid;
            g_hcur[((s & 1) ^ 1) * (BB * HH) + batch * HH + ucol] = h2;
            hout[((size_t)batch * SS + t) * HH + ucol] = h2;
        }
        __threadfence();
        grid_barrier(gridDim.x);
    }
}

// ---------------------------------------------------------------------------
// Pointer decisions: chain of argmaxes. One block per batch.
// scores[j] = tanh(q[b,j,:] + p[b,t,:]) . vt1 over j >= t; out2 is uniform
// over j, so it cannot change the argmax and is skipped.
// ---------------------------------------------------------------------------
__global__ __launch_bounds__(256) void decide_kernel(
    const float* __restrict__ q,    // [B,S,WT]
    const float* __restrict__ pm,   // [B,S,WT]
    const float* __restrict__ vt1,  // [WT]
    float* __restrict__ out)        // [S,B]
{
    const int b   = blockIdx.x;
    const int tid = threadIdx.x;
    __shared__ float pv[WT];
    __shared__ float v1[WT];
    __shared__ float rvals[256];
    __shared__ int   ridx[256];
    __shared__ int   r_sh;

    v1[tid] = vt1[tid];
    for (int s = tid; s < SS; s += 256) out[s * BB + b] = 0.f;
    __syncthreads();

    int t = 0;
    while (true) {
        pv[tid] = pm[((size_t)b * SS + t) * WT + tid];
        __syncthreads();

        float bv = -1e30f;
        int   bj = SS;
        for (int j = t + tid; j < SS; j += 256) {
            const float* qr = q + ((size_t)b * SS + j) * WT;
            float sacc = 0.f;
            for (int wi = 0; wi < WT; wi += 4) {
                float4 qq = *(const float4*)(qr + wi);
                sacc += tanhf(qq.x + pv[wi + 0]) * v1[wi + 0];
                sacc += tanhf(qq.y + pv[wi + 1]) * v1[wi + 1];
                sacc += tanhf(qq.z + pv[wi + 2]) * v1[wi + 2];
                sacc += tanhf(qq.w + pv[wi + 3]) * v1[wi + 3];
            }
            if (sacc > bv) { bv = sacc; bj = j; }   // j ascending -> first max
        }
        rvals[tid] = bv;
        ridx[tid]  = bj;
        __syncthreads();

        if (tid == 0) {
            float best = rvals[0];
            int   bi   = ridx[0];
            for (int i = 1; i < 256; i++) {
                if (rvals[i] > best || (rvals[i] == best && ridx[i] < bi)) {
                    best = rvals[i]; bi = ridx[i];
                }
            }
            out[bi * BB + b] = 1.0f;
            r_sh = bi;
        }
        __syncthreads();
        int r = r_sh;
        if (r <= t) break;   // r == t ends the chain (t passes bond forever)
        t = r;
        // pv rewrite at loop top is safe: all reads of pv happened before the
        // rvals __syncthreads above.
    }
}

// ---------------------------------------------------------------------------
// Launch
// ---------------------------------------------------------------------------
extern "C" void kernel_launch(void* const* d_in, const int* in_sizes, int n_in,
                              void* d_out, int out_size) {
    const float* x        = (const float*)d_in[0];
    const float* eWih_f   = (const float*)d_in[1];
    const float* eWhh_f   = (const float*)d_in[2];
    const float* eb_f     = (const float*)d_in[3];
    const float* eWih_b   = (const float*)d_in[4];
    const float* eWhh_b   = (const float*)d_in[5];
    const float* eb_b     = (const float*)d_in[6];
    const float* dWih     = (const float*)d_in[7];
    const float* dWhh     = (const float*)d_in[8];
    const float* db       = (const float*)d_in[9];
    const float* W1       = (const float*)d_in[10];
    const float* W2       = (const float*)d_in[11];
    const float* W3       = (const float*)d_in[12];
    const float* W4       = (const float*)d_in[13];
    const float* vt1      = (const float*)d_in[14];
    float*       out      = (float*)d_out;

    float *pre_f, *pre_b, *pre_d, *hn, *hb, *dh, *q, *p;
    cudaGetSymbolAddress((void**)&pre_f, g_pre_f);
    cudaGetSymbolAddress((void**)&pre_b, g_pre_b);
    cudaGetSymbolAddress((void**)&pre_d, g_pre_d);
    cudaGetSymbolAddress((void**)&hn,    g_hn);
    cudaGetSymbolAddress((void**)&hb,    g_hb);
    cudaGetSymbolAddress((void**)&dh,    g_dh);
    cudaGetSymbolAddress((void**)&q,     g_q);
    cudaGetSymbolAddress((void**)&p,     g_p);

    dim3 thr(256);
    dim3 gridBig(G4H / GBN, MM / GBM);   // N=1024
    dim3 gridSml(WT / GBN, MM / GBM);    // N=256

    // Phase 1: everything that depends only on x
    gemm_kernel<<<gridBig, thr>>>(x, eWih_f, eb_f, pre_f, G4H, EE, 0, 0);
    gemm_kernel<<<gridBig, thr>>>(x, eWih_b, eb_b, pre_b, G4H, EE, 0, 0);
    gemm_kernel<<<gridBig, thr>>>(x, dWih,   db,   pre_d, G4H, EE, 1, 0); // shifted x part
    gemm_kernel<<<gridSml, thr>>>(x, W3, nullptr, p, WT, EE, 0, 0);
    gemm_kernel<<<gridSml, thr>>>(x, W2, nullptr, q, WT, EE, 0, 0);

    // Forward encoder
    lstm_kernel<<<128, 512>>>(pre_f, eWhh_f, hn, nullptr, 0);

    // Depends on hn
    gemm_kernel<<<gridBig, thr>>>(hn, dWih + (size_t)EE * G4H, nullptr, pre_d, G4H, HH, 1, 1);
    gemm_kernel<<<gridSml, thr>>>(hn, W1, nullptr, q, WT, HH, 0, 1);

    // Backward encoder
    lstm_kernel<<<128, 512>>>(pre_b, eWhh_b, hb, nullptr, 1);
    gemm_kernel<<<gridSml, thr>>>(hb, W1 + (size_t)HH * WT, nullptr, q, WT, HH, 0, 1);

    // Decoder (c0 = hn[:, S-1, :])
    lstm_kernel<<<128, 512>>>(pre_d, dWhh, dh, hn, 0);
    gemm_kernel<<<gridSml, thr>>>(dh, W4, nullptr, p, WT, HH, 0, 1);

    // Decisions
    decide_kernel<<<BB, 256>>>(q, p, vt1, out);
}